// round 16
// baseline (speedup 1.0000x reference)
#include <cuda_runtime.h>
#include <cuda_fp16.h>
#include <math.h>
#include <stdint.h>

#define EPS 1e-5f
static const int HW = 112 * 112;
#define PL  ((size_t)16 * 114 * 56 * 192)   // elements per transformed plane

__device__ __half g_w1r[192 * 32];
__device__ __half g_w2t[4 * 192 * 576];     // [xi][co][ky*192+ci]
__device__ __half g_w3r[32 * 192];
__device__ __half g_h1t[4 * PL];            // 4 transformed planes (~157MB)
__device__ double g_partd[3][160];          // abs partials
__device__ double g_partd2[3][160];         // alpha partials
__device__ int    g_parti[3][160];

__device__ __forceinline__ uint32_t smem_u32(const void* p) {
    uint32_t a;
    asm("{ .reg .u64 t; cvta.to.shared.u64 t, %1; cvt.u32.u64 %0, t; }"
        : "=r"(a) : "l"(p));
    return a;
}
#define SWZ(o) ((o) ^ (((o) >> 3) & 0x70))
#define CP_ASYNC16(saddr, gaddr) \
    asm volatile("cp.async.cg.shared.global [%0], [%1], 16;" \
        :: "r"(saddr), "l"(gaddr) : "memory")
#define CP_COMMIT() asm volatile("cp.async.commit_group;" ::: "memory")
#define CP_WAIT1()  asm volatile("cp.async.wait_group 1;" ::: "memory")
#define CP_WAIT0()  asm volatile("cp.async.wait_group 0;" ::: "memory")

__device__ __forceinline__ void ldsm4(uint32_t a, uint32_t& r0, uint32_t& r1,
                                      uint32_t& r2, uint32_t& r3) {
    asm volatile("ldmatrix.sync.aligned.m8n8.x4.shared.b16 {%0,%1,%2,%3}, [%4];"
        : "=r"(r0), "=r"(r1), "=r"(r2), "=r"(r3) : "r"(a));
}
__device__ __forceinline__ void ldsm2(uint32_t a, uint32_t& r0, uint32_t& r1) {
    asm volatile("ldmatrix.sync.aligned.m8n8.x2.shared.b16 {%0,%1}, [%2];"
        : "=r"(r0), "=r"(r1) : "r"(a));
}
__device__ __forceinline__ void mma16816(float* c, uint32_t a0, uint32_t a1,
                                         uint32_t a2, uint32_t a3,
                                         uint32_t b0, uint32_t b1) {
    asm volatile(
        "mma.sync.aligned.m16n8k16.row.col.f32.f16.f16.f32 "
        "{%0,%1,%2,%3}, {%4,%5,%6,%7}, {%8,%9}, {%0,%1,%2,%3};"
        : "+f"(c[0]), "+f"(c[1]), "+f"(c[2]), "+f"(c[3])
        : "r"(a0), "r"(a1), "r"(a2), "r"(a3), "r"(b0), "r"(b1));
}

// ---------------- TWN stats pass 1: |w| partials ----------------------------
__global__ void stats_abs_all(const float* __restrict__ w1,
                              const float* __restrict__ w2,
                              const float* __restrict__ w3) {
    __shared__ double sd[256];
    int slot = blockIdx.y;
    const float* w = (slot == 0) ? w1 : (slot == 1) ? w2 : w3;
    int n = (slot == 1) ? 331776 : 6144;
    int tid = threadIdx.x;
    int g = blockIdx.x * 256 + tid, stride = gridDim.x * 256;
    double s = 0.0;
    for (int i = g; i < n; i += stride) s += (double)fabsf(w[i]);
    sd[tid] = s; __syncthreads();
    for (int o = 128; o > 0; o >>= 1) {
        if (tid < o) sd[tid] += sd[tid + o];
        __syncthreads();
    }
    if (tid == 0) g_partd[slot][blockIdx.x] = sd[0];
}

__device__ __forceinline__ float tern(float w, float delta) {
    return (fabsf(w) > delta) ? (w > 0.0f ? 1.0f : -1.0f) : 0.0f;
}

// ---------------- pass 2: inline delta + alpha partials + weight prep ------
__global__ void stats_alpha_prep(const float* __restrict__ w1,
                                 const float* __restrict__ w2,
                                 const float* __restrict__ w3) {
    __shared__ double sd[256];
    __shared__ int    si[256];
    __shared__ float  sdelta;
    int slot = blockIdx.y;
    const float* w = (slot == 0) ? w1 : (slot == 1) ? w2 : w3;
    int n = (slot == 1) ? 331776 : 6144;
    int tid = threadIdx.x;
    int g = blockIdx.x * 256 + tid, stride = gridDim.x * 256;

    // inline delta (same tree as old stats_delta_all -> bit-identical)
    sd[tid] = (tid < 148) ? g_partd[slot][tid] : 0.0;
    __syncthreads();
    for (int o = 128; o > 0; o >>= 1) {
        if (tid < o) sd[tid] += sd[tid + o];
        __syncthreads();
    }
    if (tid == 0) sdelta = (float)(0.7 * sd[0] / (double)n);
    __syncthreads();
    float delta = sdelta;
    __syncthreads();

    // alpha partials (write to SEPARATE arrays to avoid racing abs partials)
    double s = 0.0; int c = 0;
    for (int i = g; i < n; i += stride) {
        float a = fabsf(w[i]);
        if (a > delta) { s += (double)a; c++; }
    }
    sd[tid] = s; si[tid] = c; __syncthreads();
    for (int o = 128; o > 0; o >>= 1) {
        if (tid < o) { sd[tid] += sd[tid + o]; si[tid] += si[tid + o]; }
        __syncthreads();
    }
    if (tid == 0) { g_partd2[slot][blockIdx.x] = sd[0]; g_parti[slot][blockIdx.x] = si[0]; }

    // ---- fused prep (L2-hot re-read) ----
    if (slot == 1) {
        for (int i = g; i < 110592; i += stride) {
            int co = i / 576; int rem = i - co * 576;
            int ci = rem / 3;  int ky = rem - ci * 3;
            const float* wp = w2 + ((size_t)(co * 192 + ci) * 3 + ky) * 3;
            float q0 = tern(wp[0], delta);
            float q1 = tern(wp[1], delta);
            float q2 = tern(wp[2], delta);
            __half* o = g_w2t + (size_t)co * 576 + (size_t)ky * 192 + ci;
            o[0]      = __float2half_rn(q0);
            o[110592] = __float2half_rn(0.5f * (q0 + q1 + q2));
            o[221184] = __float2half_rn(0.5f * (q0 - q1 + q2));
            o[331776] = __float2half_rn(q2);
        }
    } else if (slot == 0) {
        for (int i = g; i < 6144; i += stride)
            g_w1r[i] = __float2half_rn(tern(w1[i], delta));
    } else {
        for (int i = g; i < 6144; i += stride)
            g_w3r[i] = __float2half_rn(tern(w3[i], delta));
    }
}

// inline alpha reduce (identical tree to old stats_alpha_fin_all)
__device__ __forceinline__ float alpha_reduce(int slot, double* sd, int* si,
                                              int tid) {
    if (tid < 256) {
        sd[tid] = (tid < 148) ? g_partd2[slot][tid] : 0.0;
        si[tid] = (tid < 148) ? g_parti[slot][tid] : 0;
    }
    __syncthreads();
    for (int o = 128; o > 0; o >>= 1) {
        if (tid < o) { sd[tid] += sd[tid + o]; si[tid] += si[tid + o]; }
        __syncthreads();
    }
    int cnt = si[0] < 1 ? 1 : si[0];
    float a = (float)(sd[0] / (double)cnt);
    __syncthreads();
    return a;
}

// ---------------- conv1w: 1x1 HMMA per row + x-transform -> g_h1t ----------
#define W1_BN  0
#define W1_A   2048
#define W1_B   16384
#define W1_HR  40960
#define W1_SMEM 85504

__global__ __launch_bounds__(256) void conv1w(
    const float* __restrict__ x,
    const float* __restrict__ g1, const float* __restrict__ b1,
    const float* __restrict__ m1, const float* __restrict__ v1)
{
    extern __shared__ char dsm[];
    uint32_t sb = (smem_u32(dsm) + 1023u) & ~1023u;
    char* sbase = dsm + (sb - smem_u32(dsm));
    float*  bnS  = (float*)(sbase + W1_BN);
    __half* hrow = (__half*)(sbase + W1_HR);

    int tid = threadIdx.x, wid = tid >> 5, lane = tid & 31;
    int img = blockIdx.y;
    int y   = blockIdx.x;

    for (int i = tid; i < 768; i += 256) {
        int row = i >> 2, c16 = i & 3;
        CP_ASYNC16(sb + W1_B + SWZ(row * 128 + c16 * 16),
                   (const char*)(g_w1r + row * 32) + c16 * 16);
    }
    CP_COMMIT();

    // alpha1 inline (scratch in hrow region, free until zero-init below)
    float alpha1 = alpha_reduce(0, (double*)(sbase + W1_HR),
                                (int*)(sbase + W1_HR + 2048), tid);

    for (int c = tid; c < 192; c += 256) {
        float is = rsqrtf(v1[c] + EPS);
        bnS[c]       = alpha1 * g1[c] * is;
        bnS[192 + c] = b1[c] - m1[c] * g1[c] * is;
    }
    if (tid < 192) {
        hrow[tid] = __ushort_as_half(0);
        hrow[113 * 194 + tid] = __ushort_as_half(0);
    }

    const float* xr = x + (size_t)img * 32 * HW + (size_t)y * 112;
#pragma unroll
    for (int it = 0; it < 7; it++) {
        int idx = it * 256 + tid;            // < 1792 = 112*16
        int pix = idx >> 4, cp = idx & 15;
        float f0 = xr[(size_t)(2 * cp) * HW + pix];
        float f1 = xr[(size_t)(2 * cp + 1) * HW + pix];
        uint32_t pk = (uint32_t)__half_as_ushort(__float2half_rn(f0)) |
                      ((uint32_t)__half_as_ushort(__float2half_rn(f1)) << 16);
        *(uint32_t*)(sbase + W1_A + SWZ(pix * 128 + cp * 4)) = pk;
    }
    CP_WAIT0();
    __syncthreads();

    int wn = wid * 24;
    float acc[7][3][4];
#pragma unroll
    for (int a = 0; a < 7; a++)
#pragma unroll
        for (int b = 0; b < 3; b++)
#pragma unroll
            for (int c = 0; c < 4; c++) acc[a][b][c] = 0.0f;

#pragma unroll
    for (int kk = 0; kk < 2; kk++) {
        uint32_t bf[3][2];
        {
            uint32_t q0, q1, q2, q3;
            ldsm4(sb + W1_B + SWZ((wn + ((lane >> 4) & 1) * 8 + (lane & 7)) * 128 +
                                  (kk * 16 + ((lane >> 3) & 1) * 8) * 2),
                  q0, q1, q2, q3);
            bf[0][0] = q0; bf[0][1] = q1; bf[1][0] = q2; bf[1][1] = q3;
        }
        {
            uint32_t q0, q1;
            ldsm2(sb + W1_B + SWZ((wn + 16 + (lane & 7)) * 128 +
                                  (kk * 16 + ((lane >> 3) & 1) * 8) * 2), q0, q1);
            bf[2][0] = q0; bf[2][1] = q1;
        }
#pragma unroll
        for (int mi = 0; mi < 7; mi++) {
            int m_loc = mi * 16 + (lane & 7) + ((lane >> 3) & 1) * 8;
            int kh = kk * 16 + (lane >> 4) * 8;
            uint32_t a0, a1, a2, a3;
            ldsm4(sb + W1_A + SWZ(m_loc * 128 + kh * 2), a0, a1, a2, a3);
#pragma unroll
            for (int ni = 0; ni < 3; ni++)
                mma16816(acc[mi][ni], a0, a1, a2, a3, bf[ni][0], bf[ni][1]);
        }
    }

    // BN1 + ReLU6 -> hrow[xidx = pix+1][192]
#pragma unroll
    for (int mi = 0; mi < 7; mi++) {
#pragma unroll
        for (int h = 0; h < 2; h++) {
            int m = mi * 16 + (lane >> 2) + h * 8;
#pragma unroll
            for (int ni = 0; ni < 3; ni++) {
                int c = wn + ni * 8 + 2 * (lane & 3);
                float y0 = fmaf(acc[mi][ni][h * 2 + 0], bnS[c],     bnS[192 + c]);
                float y1 = fmaf(acc[mi][ni][h * 2 + 1], bnS[c + 1], bnS[192 + c + 1]);
                y0 = fminf(fmaxf(y0, 0.0f), 6.0f);
                y1 = fminf(fmaxf(y1, 0.0f), 6.0f);
                uint32_t pk = (uint32_t)__half_as_ushort(__float2half_rn(y0)) |
                              ((uint32_t)__half_as_ushort(__float2half_rn(y1)) << 16);
                *(uint32_t*)((char*)hrow + ((m + 1) * 194 + c) * 2) = pk;
            }
        }
    }
    __syncthreads();

    // x-transform -> 4 planes at row yp = y+1
    size_t base0 = (((size_t)img) * 114 + (y + 1)) * 56 * 192;
#pragma unroll
    for (int it = 0; it < 21; it++) {
        int i = it * 256 + tid;              // < 5376 = 56*96
        int px = i / 96, cp = i - px * 96;
        const char* hb = (const char*)hrow + (2 * px) * 388 + cp * 4;
        __half2 d0 = *(const __half2*)hb;
        __half2 d1 = *(const __half2*)(hb + 388);
        __half2 d2 = *(const __half2*)(hb + 776);
        __half2 d3 = *(const __half2*)(hb + 1164);
        size_t off = base0 + (size_t)px * 192 + 2 * cp;
        *(__half2*)(g_h1t + off)          = __hsub2(d0, d2);
        *(__half2*)(g_h1t + off + PL)     = __hadd2(d1, d2);
        *(__half2*)(g_h1t + off + 2 * PL) = __hsub2(d2, d1);
        *(__half2*)(g_h1t + off + 3 * PL) = __hsub2(d1, d3);
    }
}

// ---------------- conv2 winograd-x + conv3 fused ----------------------------
#define G_BN2  0
#define G_BN3  1536
#define G_W3   2048
#define G_U    14336
#define G_H2S  14336
#define G_RING 89600
#define G_SMEM 200704

__global__ __launch_bounds__(384, 1) void conv2w3(
    const float* __restrict__ g2, const float* __restrict__ b2,
    const float* __restrict__ m2p, const float* __restrict__ v2,
    const float* __restrict__ g3, const float* __restrict__ b3,
    const float* __restrict__ m3p, const float* __restrict__ v3,
    const float* __restrict__ x, float* __restrict__ out)
{
    extern __shared__ char dsm[];
    uint32_t sb = (smem_u32(dsm) + 1023u) & ~1023u;
    char* sbase = dsm + (sb - smem_u32(dsm));
    float* bn2 = (float*)(sbase + G_BN2);
    float* bn3 = (float*)(sbase + G_BN3);

    int tid = threadIdx.x, wid = tid >> 5, lane = tid & 31;
    int img   = blockIdx.y;
    int pbase = blockIdx.x * 96;

    // alpha2/alpha3 inline (scratch in G_U region, free until mainloop)
    float alpha2 = alpha_reduce(1, (double*)(sbase + G_U),
                                (int*)(sbase + G_U + 2048), tid);
    float alpha3 = alpha_reduce(2, (double*)(sbase + G_U),
                                (int*)(sbase + G_U + 2048), tid);

    for (int i = tid; i < 768; i += 384) {
        int ch = i >> 8; int rem = i & 255;
        int row = rem >> 3, c16 = rem & 7;
        uint4 v = *(const uint4*)((const char*)(g_w3r + row * 192 + ch * 64) + c16 * 16);
        *(uint4*)(sbase + G_W3 + ch * 4096 + SWZ(row * 128 + c16 * 16)) = v;
    }
    for (int c = tid; c < 192; c += 384) {
        float is = rsqrtf(v2[c] + EPS);
        bn2[c]       = alpha2 * g2[c] * is;
        bn2[192 + c] = b2[c] - m2p[c] * g2[c] * is;
    }
    if (tid < 32) {
        float is = rsqrtf(v3[tid] + EPS);
        bn3[tid]      = alpha3 * g3[tid] * is;
        bn3[32 + tid] = b3[tid] - m3p[tid] * g3[tid] * is;
    }

    auto load_chunk = [&](int t) {
        int ph = t / 9;
        int xi = (ph == 0) ? 2 : (ph == 1) ? 1 : (ph == 2) ? 0 : 3;
        int kc = t - ph * 9;
        int ky = kc / 3, ch = kc - ky * 3;
        int st = t % 3;
        uint32_t dA = sb + G_RING + st * 36864;
        uint32_t dB = dA + 12288;
        const __half* bsrc = g_w2t + (size_t)xi * 110592 + ky * 192 + ch * 64;
#pragma unroll
        for (int pp = 0; pp < 2; pp++) {
            int lin = pp * 384 + tid;
            int row = lin >> 3, c16 = lin & 7;
            int p = pbase + row; p = (p < 6271) ? p : 6271;
            int yq = p / 56; int pxq = p - yq * 56;
            const __half* asrc = g_h1t + (size_t)xi * PL +
                ((((size_t)img) * 114 + (yq + ky)) * 56 + pxq) * 192 + ch * 64;
            CP_ASYNC16(dA + SWZ(row * 128 + c16 * 16), (const char*)asrc + c16 * 16);
        }
#pragma unroll
        for (int pp = 0; pp < 4; pp++) {
            int lin = pp * 384 + tid;
            int row = lin >> 3, c16 = lin & 7;
            CP_ASYNC16(dB + SWZ(row * 128 + c16 * 16),
                       (const char*)(bsrc + (size_t)row * 576) + c16 * 16);
        }
    };

    int wm = (wid >= 6) ? 48 : 0;
    int wn = (wid % 6) * 32;

    int bR    = wn + ((lane >> 4) & 1) * 8 + (lane & 7);
    int bKsel = ((lane >> 3) & 1) * 8;
    int aM    = wm + (lane & 7) + ((lane >> 3) & 1) * 8;
    int aKsel = (lane >> 4) * 8;

    float acc[3][4][4], r3[3][4][4];
#pragma unroll
    for (int a = 0; a < 3; a++)
#pragma unroll
        for (int b = 0; b < 4; b++)
#pragma unroll
            for (int c = 0; c < 4; c++) { acc[a][b][c] = 0.0f; r3[a][b][c] = 0.0f; }

    float* uptr = (float*)(sbase + G_U + tid * 196);
    char*  h2s  = sbase + G_H2S;

    load_chunk(0); CP_COMMIT();
    load_chunk(1); CP_COMMIT();

    for (int t = 0; t < 36; t++) {
        if (t == 35) { CP_WAIT0(); } else { CP_WAIT1(); }
        __syncthreads();
        if (t + 2 < 36) { load_chunk(t + 2); CP_COMMIT(); }

        int st = t % 3;
        uint32_t cA = sb + G_RING + st * 36864;
        uint32_t cB = cA + 12288;
#pragma unroll
        for (int kk = 0; kk < 4; kk++) {
            uint32_t bf[4][2];
#pragma unroll
            for (int bb = 0; bb < 2; bb++) {
                uint32_t q0, q1, q2, q3;
                ldsm4(cB + SWZ((bR + bb * 16) * 128 + (kk * 16 + bKsel) * 2),
                      q0, q1, q2, q3);
                bf[2 * bb][0] = q0; bf[2 * bb][1] = q1;
                bf[2 * bb + 1][0] = q2; bf[2 * bb + 1][1] = q3;
            }
#pragma unroll
            for (int mi = 0; mi < 3; mi++) {
                uint32_t a0, a1, a2, a3;
                ldsm4(cA + SWZ((aM + mi * 16) * 128 + (kk * 16 + aKsel) * 2),
                      a0, a1, a2, a3);
#pragma unroll
                for (int ni = 0; ni < 4; ni++)
                    mma16816(acc[mi][ni], a0, a1, a2, a3, bf[ni][0], bf[ni][1]);
            }
        }

        if (t == 8) {
#pragma unroll
            for (int a = 0; a < 3; a++)
#pragma unroll
                for (int b = 0; b < 4; b++)
#pragma unroll
                    for (int c = 0; c < 4; c++) { r3[a][b][c] = acc[a][b][c]; acc[a][b][c] = 0.0f; }
        } else if (t == 17) {
#pragma unroll
            for (int a = 0; a < 3; a++)
#pragma unroll
                for (int b = 0; b < 4; b++)
#pragma unroll
                    for (int c = 0; c < 4; c++) {
                        int j = (a * 4 + b) * 4 + c;
                        uptr[j] = acc[a][b][c] + r3[a][b][c];
                        r3[a][b][c] = acc[a][b][c] - r3[a][b][c];
                        acc[a][b][c] = 0.0f;
                    }
        } else if (t == 26) {
#pragma unroll
            for (int a = 0; a < 3; a++)
#pragma unroll
                for (int b = 0; b < 4; b++)
#pragma unroll
                    for (int c = 0; c < 4; c++)
                        acc[a][b][c] += uptr[(a * 4 + b) * 4 + c];
            __syncthreads();
#pragma unroll
            for (int mi = 0; mi < 3; mi++) {
#pragma unroll
                for (int h = 0; h < 2; h++) {
                    int m = 2 * (wm + mi * 16 + (lane >> 2) + h * 8);
#pragma unroll
                    for (int ni = 0; ni < 4; ni++) {
                        int cc = wn + ni * 8 + 2 * (lane & 3);
                        float y0 = fmaf(acc[mi][ni][h * 2 + 0], bn2[cc],     bn2[192 + cc]);
                        float y1 = fmaf(acc[mi][ni][h * 2 + 1], bn2[cc + 1], bn2[192 + cc + 1]);
                        y0 = fminf(fmaxf(y0, 0.0f), 6.0f);
                        y1 = fminf(fmaxf(y1, 0.0f), 6.0f);
                        uint32_t pk = (uint32_t)__half_as_ushort(__float2half_rn(y0)) |
                                      ((uint32_t)__half_as_ushort(__float2half_rn(y1)) << 16);
                        *(uint32_t*)(h2s + (cc >> 6) * 24576 + SWZ(m * 128 + (cc & 63) * 2)) = pk;
                    }
                }
            }
#pragma unroll
            for (int a = 0; a < 3; a++)
#pragma unroll
                for (int b = 0; b < 4; b++)
#pragma unroll
                    for (int c = 0; c < 4; c++) acc[a][b][c] = 0.0f;
        }
    }
#pragma unroll
    for (int mi = 0; mi < 3; mi++) {
#pragma unroll
        for (int h = 0; h < 2; h++) {
            int m = 2 * (wm + mi * 16 + (lane >> 2) + h * 8) + 1;
#pragma unroll
            for (int ni = 0; ni < 4; ni++) {
                int cc = wn + ni * 8 + 2 * (lane & 3);
                float y0 = fmaf(r3[mi][ni][h * 2 + 0] - acc[mi][ni][h * 2 + 0],
                                bn2[cc],     bn2[192 + cc]);
                float y1 = fmaf(r3[mi][ni][h * 2 + 1] - acc[mi][ni][h * 2 + 1],
                                bn2[cc + 1], bn2[192 + cc + 1]);
                y0 = fminf(fmaxf(y0, 0.0f), 6.0f);
                y1 = fminf(fmaxf(y1, 0.0f), 6.0f);
                uint32_t pk = (uint32_t)__half_as_ushort(__float2half_rn(y0)) |
                              ((uint32_t)__half_as_ushort(__float2half_rn(y1)) << 16);
                *(uint32_t*)(h2s + (cc >> 6) * 24576 + SWZ(m * 128 + (cc & 63) * 2)) = pk;
            }
        }
    }
    __syncthreads();

    int wm3 = (wid >> 2) * 64;
    int wn3 = (wid & 3) * 8;
    float acc3[4][4];
#pragma unroll
    for (int a = 0; a < 4; a++)
#pragma unroll
        for (int c = 0; c < 4; c++) acc3[a][c] = 0.0f;

#pragma unroll
    for (int ch = 0; ch < 3; ch++) {
        uint32_t cA = sb + G_H2S + ch * 24576;
        uint32_t cB = sb + G_W3 + ch * 4096;
#pragma unroll
        for (int kk = 0; kk < 4; kk++) {
            uint32_t b0, b1;
            ldsm2(cB + SWZ((wn3 + (lane & 7)) * 128 +
                           (kk * 16 + ((lane >> 3) & 1) * 8) * 2), b0, b1);
#pragma unroll
            for (int mi = 0; mi < 4; mi++) {
                int m_loc = wm3 + mi * 16 + (lane & 7) + ((lane >> 3) & 1) * 8;
                int kh = kk * 16 + (lane >> 4) * 8;
                uint32_t a0, a1, a2, a3;
                ldsm4(cA + SWZ(m_loc * 128 + kh * 2), a0, a1, a2, a3);
                mma16816(acc3[mi], a0, a1, a2, a3, b0, b1);
            }
        }
    }

    const float* xi = x + (size_t)img * 32 * HW;
    float* oi = out + (size_t)img * 32 * HW;
#pragma unroll
    for (int mi = 0; mi < 4; mi++) {
#pragma unroll
        for (int h = 0; h < 2; h++) {
            int m = wm3 + mi * 16 + (lane >> 2) + h * 8;
            int P = pbase + (m >> 1);
            if (P < 6272) {
                int yq = P / 56, px = P - yq * 56;
                int pix = yq * 112 + 2 * px + (m & 1);
                int c = wn3 + 2 * (lane & 3);
                size_t i0 = (size_t)c * HW + pix;
                size_t i1 = i0 + HW;
                oi[i0] = fmaf(acc3[mi][h * 2 + 0], bn3[c],     bn3[32 + c])     + xi[i0];
                oi[i1] = fmaf(acc3[mi][h * 2 + 1], bn3[c + 1], bn3[32 + c + 1]) + xi[i1];
            }
        }
    }
}

// ---------------- launch ----------------------------------------------------
extern "C" void kernel_launch(void* const* d_in, const int* in_sizes, int n_in,
                              void* d_out, int out_size) {
    const float* x  = (const float*)d_in[0];
    const float* w1 = (const float*)d_in[1];
    const float* g1 = (const float*)d_in[2];
    const float* b1 = (const float*)d_in[3];
    const float* m1 = (const float*)d_in[4];
    const float* v1 = (const float*)d_in[5];
    const float* w2 = (const float*)d_in[6];
    const float* g2 = (const float*)d_in[7];
    const float* b2 = (const float*)d_in[8];
    const float* m2 = (const float*)d_in[9];
    const float* v2 = (const float*)d_in[10];
    const float* w3 = (const float*)d_in[11];
    const float* g3 = (const float*)d_in[12];
    const float* b3 = (const float*)d_in[13];
    const float* m3 = (const float*)d_in[14];
    const float* v3 = (const float*)d_in[15];
    float* out = (float*)d_out;

    cudaFuncSetAttribute(conv1w, cudaFuncAttributeMaxDynamicSharedMemorySize, W1_SMEM);
    cudaFuncSetAttribute(conv2w3, cudaFuncAttributeMaxDynamicSharedMemorySize, G_SMEM);

    stats_abs_all<<<dim3(148, 3), 256>>>(w1, w2, w3);
    stats_alpha_prep<<<dim3(148, 3), 256>>>(w1, w2, w3);

    conv1w<<<dim3(112, 16), 256, W1_SMEM>>>(x, g1, b1, m1, v1);
    conv2w3<<<dim3(66, 16), 384, G_SMEM>>>(g2, b2, m2, v2,
                                           g3, b3, m3, v3, x, out);
}

// round 17
// speedup vs baseline: 1.1709x; 1.1709x over previous
#include <cuda_runtime.h>
#include <cuda_fp16.h>
#include <math.h>
#include <stdint.h>

#define EPS 1e-5f
static const int HW = 112 * 112;
#define PL  ((size_t)16 * 114 * 56 * 192)   // elements per transformed plane

__device__ __half g_w1r[192 * 32];
__device__ __half g_w2t[4 * 192 * 576];     // [xi][co][ky*192+ci]
__device__ __half g_w3r[32 * 192];
__device__ __half g_h1t[4 * PL];            // 4 transformed planes (~157MB)
__device__ float  g_alpha[3];
__device__ double g_partd[3][160];          // abs partials
__device__ double g_partd2[3][160];         // alpha partials
__device__ int    g_parti[3][160];

__device__ __forceinline__ uint32_t smem_u32(const void* p) {
    uint32_t a;
    asm("{ .reg .u64 t; cvta.to.shared.u64 t, %1; cvt.u32.u64 %0, t; }"
        : "=r"(a) : "l"(p));
    return a;
}
#define SWZ(o) ((o) ^ (((o) >> 3) & 0x70))
#define CP_ASYNC16(saddr, gaddr) \
    asm volatile("cp.async.cg.shared.global [%0], [%1], 16;" \
        :: "r"(saddr), "l"(gaddr) : "memory")
#define CP_COMMIT() asm volatile("cp.async.commit_group;" ::: "memory")
#define CP_WAIT1()  asm volatile("cp.async.wait_group 1;" ::: "memory")
#define CP_WAIT0()  asm volatile("cp.async.wait_group 0;" ::: "memory")

__device__ __forceinline__ void ldsm4(uint32_t a, uint32_t& r0, uint32_t& r1,
                                      uint32_t& r2, uint32_t& r3) {
    asm volatile("ldmatrix.sync.aligned.m8n8.x4.shared.b16 {%0,%1,%2,%3}, [%4];"
        : "=r"(r0), "=r"(r1), "=r"(r2), "=r"(r3) : "r"(a));
}
__device__ __forceinline__ void ldsm2(uint32_t a, uint32_t& r0, uint32_t& r1) {
    asm volatile("ldmatrix.sync.aligned.m8n8.x2.shared.b16 {%0,%1}, [%2];"
        : "=r"(r0), "=r"(r1) : "r"(a));
}
__device__ __forceinline__ void mma16816(float* c, uint32_t a0, uint32_t a1,
                                         uint32_t a2, uint32_t a3,
                                         uint32_t b0, uint32_t b1) {
    asm volatile(
        "mma.sync.aligned.m16n8k16.row.col.f32.f16.f16.f32 "
        "{%0,%1,%2,%3}, {%4,%5,%6,%7}, {%8,%9}, {%0,%1,%2,%3};"
        : "+f"(c[0]), "+f"(c[1]), "+f"(c[2]), "+f"(c[3])
        : "r"(a0), "r"(a1), "r"(a2), "r"(a3), "r"(b0), "r"(b1));
}

// ---------------- TWN stats pass 1: |w| partials ----------------------------
__global__ void stats_abs_all(const float* __restrict__ w1,
                              const float* __restrict__ w2,
                              const float* __restrict__ w3) {
    __shared__ double sd[256];
    int slot = blockIdx.y;
    const float* w = (slot == 0) ? w1 : (slot == 1) ? w2 : w3;
    int n = (slot == 1) ? 331776 : 6144;
    int tid = threadIdx.x;
    int g = blockIdx.x * 256 + tid, stride = gridDim.x * 256;
    double s = 0.0;
    for (int i = g; i < n; i += stride) s += (double)fabsf(w[i]);
    sd[tid] = s; __syncthreads();
    for (int o = 128; o > 0; o >>= 1) {
        if (tid < o) sd[tid] += sd[tid + o];
        __syncthreads();
    }
    if (tid == 0) g_partd[slot][blockIdx.x] = sd[0];
}

__device__ __forceinline__ float tern(float w, float delta) {
    return (fabsf(w) > delta) ? (w > 0.0f ? 1.0f : -1.0f) : 0.0f;
}

// ---------------- pass 2: inline delta + alpha partials + weight prep ------
__global__ void stats_alpha_prep(const float* __restrict__ w1,
                                 const float* __restrict__ w2,
                                 const float* __restrict__ w3) {
    __shared__ double sd[256];
    __shared__ int    si[256];
    __shared__ float  sdelta;
    int slot = blockIdx.y;
    const float* w = (slot == 0) ? w1 : (slot == 1) ? w2 : w3;
    int n = (slot == 1) ? 331776 : 6144;
    int tid = threadIdx.x;
    int g = blockIdx.x * 256 + tid, stride = gridDim.x * 256;

    // inline delta (same tree as old stats_delta_all -> bit-identical)
    sd[tid] = (tid < 148) ? g_partd[slot][tid] : 0.0;
    __syncthreads();
    for (int o = 128; o > 0; o >>= 1) {
        if (tid < o) sd[tid] += sd[tid + o];
        __syncthreads();
    }
    if (tid == 0) sdelta = (float)(0.7 * sd[0] / (double)n);
    __syncthreads();
    float delta = sdelta;
    __syncthreads();

    // alpha partials (SEPARATE arrays: no race with abs partials)
    double s = 0.0; int c = 0;
    for (int i = g; i < n; i += stride) {
        float a = fabsf(w[i]);
        if (a > delta) { s += (double)a; c++; }
    }
    sd[tid] = s; si[tid] = c; __syncthreads();
    for (int o = 128; o > 0; o >>= 1) {
        if (tid < o) { sd[tid] += sd[tid + o]; si[tid] += si[tid + o]; }
        __syncthreads();
    }
    if (tid == 0) { g_partd2[slot][blockIdx.x] = sd[0]; g_parti[slot][blockIdx.x] = si[0]; }

    // ---- fused prep (L2-hot re-read) ----
    if (slot == 1) {
        for (int i = g; i < 110592; i += stride) {
            int co = i / 576; int rem = i - co * 576;
            int ci = rem / 3;  int ky = rem - ci * 3;
            const float* wp = w2 + ((size_t)(co * 192 + ci) * 3 + ky) * 3;
            float q0 = tern(wp[0], delta);
            float q1 = tern(wp[1], delta);
            float q2 = tern(wp[2], delta);
            __half* o = g_w2t + (size_t)co * 576 + (size_t)ky * 192 + ci;
            o[0]      = __float2half_rn(q0);
            o[110592] = __float2half_rn(0.5f * (q0 + q1 + q2));
            o[221184] = __float2half_rn(0.5f * (q0 - q1 + q2));
            o[331776] = __float2half_rn(q2);
        }
    } else if (slot == 0) {
        for (int i = g; i < 6144; i += stride)
            g_w1r[i] = __float2half_rn(tern(w1[i], delta));
    } else {
        for (int i = g; i < 6144; i += stride)
            g_w3r[i] = __float2half_rn(tern(w3[i], delta));
    }
}

// ---------------- pass 3: tiny alpha finalize (grid 3) ---------------------
__global__ void stats_alpha_fin_all() {
    __shared__ double sd[256];
    __shared__ int    si[256];
    int slot = blockIdx.x;
    int tid = threadIdx.x;
    sd[tid] = (tid < 148) ? g_partd2[slot][tid] : 0.0;
    si[tid] = (tid < 148) ? g_parti[slot][tid] : 0;
    __syncthreads();
    for (int o = 128; o > 0; o >>= 1) {
        if (tid < o) { sd[tid] += sd[tid + o]; si[tid] += si[tid + o]; }
        __syncthreads();
    }
    if (tid == 0) {
        int cnt = si[0] < 1 ? 1 : si[0];
        g_alpha[slot] = (float)(sd[0] / (double)cnt);
    }
}

// ---------------- conv1w: 1x1 HMMA per row + x-transform -> g_h1t ----------
// (exact R15 version)
#define W1_BN  0
#define W1_A   2048
#define W1_B   16384
#define W1_HR  40960
#define W1_SMEM 85504

__global__ __launch_bounds__(256) void conv1w(
    const float* __restrict__ x,
    const float* __restrict__ g1, const float* __restrict__ b1,
    const float* __restrict__ m1, const float* __restrict__ v1)
{
    extern __shared__ char dsm[];
    uint32_t sb = (smem_u32(dsm) + 1023u) & ~1023u;
    char* sbase = dsm + (sb - smem_u32(dsm));
    float*  bnS  = (float*)(sbase + W1_BN);
    __half* hrow = (__half*)(sbase + W1_HR);

    int tid = threadIdx.x, wid = tid >> 5, lane = tid & 31;
    int img = blockIdx.y;
    int y   = blockIdx.x;

    for (int i = tid; i < 768; i += 256) {
        int row = i >> 2, c16 = i & 3;
        CP_ASYNC16(sb + W1_B + SWZ(row * 128 + c16 * 16),
                   (const char*)(g_w1r + row * 32) + c16 * 16);
    }
    CP_COMMIT();

    float alpha1 = g_alpha[0];
    for (int c = tid; c < 192; c += 256) {
        float is = rsqrtf(v1[c] + EPS);
        bnS[c]       = alpha1 * g1[c] * is;
        bnS[192 + c] = b1[c] - m1[c] * g1[c] * is;
    }
    if (tid < 192) {
        hrow[tid] = __ushort_as_half(0);
        hrow[113 * 194 + tid] = __ushort_as_half(0);
    }

    const float* xr = x + (size_t)img * 32 * HW + (size_t)y * 112;
#pragma unroll
    for (int it = 0; it < 7; it++) {
        int idx = it * 256 + tid;            // < 1792 = 112*16
        int pix = idx >> 4, cp = idx & 15;
        float f0 = xr[(size_t)(2 * cp) * HW + pix];
        float f1 = xr[(size_t)(2 * cp + 1) * HW + pix];
        uint32_t pk = (uint32_t)__half_as_ushort(__float2half_rn(f0)) |
                      ((uint32_t)__half_as_ushort(__float2half_rn(f1)) << 16);
        *(uint32_t*)(sbase + W1_A + SWZ(pix * 128 + cp * 4)) = pk;
    }
    CP_WAIT0();
    __syncthreads();

    int wn = wid * 24;
    float acc[7][3][4];
#pragma unroll
    for (int a = 0; a < 7; a++)
#pragma unroll
        for (int b = 0; b < 3; b++)
#pragma unroll
            for (int c = 0; c < 4; c++) acc[a][b][c] = 0.0f;

#pragma unroll
    for (int kk = 0; kk < 2; kk++) {
        uint32_t bf[3][2];
        {
            uint32_t q0, q1, q2, q3;
            ldsm4(sb + W1_B + SWZ((wn + ((lane >> 4) & 1) * 8 + (lane & 7)) * 128 +
                                  (kk * 16 + ((lane >> 3) & 1) * 8) * 2),
                  q0, q1, q2, q3);
            bf[0][0] = q0; bf[0][1] = q1; bf[1][0] = q2; bf[1][1] = q3;
        }
        {
            uint32_t q0, q1;
            ldsm2(sb + W1_B + SWZ((wn + 16 + (lane & 7)) * 128 +
                                  (kk * 16 + ((lane >> 3) & 1) * 8) * 2), q0, q1);
            bf[2][0] = q0; bf[2][1] = q1;
        }
#pragma unroll
        for (int mi = 0; mi < 7; mi++) {
            int m_loc = mi * 16 + (lane & 7) + ((lane >> 3) & 1) * 8;
            int kh = kk * 16 + (lane >> 4) * 8;
            uint32_t a0, a1, a2, a3;
            ldsm4(sb + W1_A + SWZ(m_loc * 128 + kh * 2), a0, a1, a2, a3);
#pragma unroll
            for (int ni = 0; ni < 3; ni++)
                mma16816(acc[mi][ni], a0, a1, a2, a3, bf[ni][0], bf[ni][1]);
        }
    }

    // BN1 + ReLU6 -> hrow[xidx = pix+1][192]
#pragma unroll
    for (int mi = 0; mi < 7; mi++) {
#pragma unroll
        for (int h = 0; h < 2; h++) {
            int m = mi * 16 + (lane >> 2) + h * 8;
#pragma unroll
            for (int ni = 0; ni < 3; ni++) {
                int c = wn + ni * 8 + 2 * (lane & 3);
                float y0 = fmaf(acc[mi][ni][h * 2 + 0], bnS[c],     bnS[192 + c]);
                float y1 = fmaf(acc[mi][ni][h * 2 + 1], bnS[c + 1], bnS[192 + c + 1]);
                y0 = fminf(fmaxf(y0, 0.0f), 6.0f);
                y1 = fminf(fmaxf(y1, 0.0f), 6.0f);
                uint32_t pk = (uint32_t)__half_as_ushort(__float2half_rn(y0)) |
                              ((uint32_t)__half_as_ushort(__float2half_rn(y1)) << 16);
                *(uint32_t*)((char*)hrow + ((m + 1) * 194 + c) * 2) = pk;
            }
        }
    }
    __syncthreads();

    // x-transform -> 4 planes at row yp = y+1
    size_t base0 = (((size_t)img) * 114 + (y + 1)) * 56 * 192;
#pragma unroll
    for (int it = 0; it < 21; it++) {
        int i = it * 256 + tid;              // < 5376 = 56*96
        int px = i / 96, cp = i - px * 96;
        const char* hb = (const char*)hrow + (2 * px) * 388 + cp * 4;
        __half2 d0 = *(const __half2*)hb;
        __half2 d1 = *(const __half2*)(hb + 388);
        __half2 d2 = *(const __half2*)(hb + 776);
        __half2 d3 = *(const __half2*)(hb + 1164);
        size_t off = base0 + (size_t)px * 192 + 2 * cp;
        *(__half2*)(g_h1t + off)          = __hsub2(d0, d2);
        *(__half2*)(g_h1t + off + PL)     = __hadd2(d1, d2);
        *(__half2*)(g_h1t + off + 2 * PL) = __hsub2(d2, d1);
        *(__half2*)(g_h1t + off + 3 * PL) = __hsub2(d1, d3);
    }
}

// ---------------- conv2 winograd-x + conv3 fused (exact R15 version) -------
#define G_BN2  0
#define G_BN3  1536
#define G_W3   2048
#define G_U    14336
#define G_H2S  14336
#define G_RING 89600
#define G_SMEM 200704

__global__ __launch_bounds__(384, 1) void conv2w3(
    const float* __restrict__ g2, const float* __restrict__ b2,
    const float* __restrict__ m2p, const float* __restrict__ v2,
    const float* __restrict__ g3, const float* __restrict__ b3,
    const float* __restrict__ m3p, const float* __restrict__ v3,
    const float* __restrict__ x, float* __restrict__ out)
{
    extern __shared__ char dsm[];
    uint32_t sb = (smem_u32(dsm) + 1023u) & ~1023u;
    char* sbase = dsm + (sb - smem_u32(dsm));
    float* bn2 = (float*)(sbase + G_BN2);
    float* bn3 = (float*)(sbase + G_BN3);

    int tid = threadIdx.x, wid = tid >> 5, lane = tid & 31;
    int img   = blockIdx.y;
    int pbase = blockIdx.x * 96;

    for (int i = tid; i < 768; i += 384) {
        int ch = i >> 8; int rem = i & 255;
        int row = rem >> 3, c16 = rem & 7;
        uint4 v = *(const uint4*)((const char*)(g_w3r + row * 192 + ch * 64) + c16 * 16);
        *(uint4*)(sbase + G_W3 + ch * 4096 + SWZ(row * 128 + c16 * 16)) = v;
    }
    float alpha2 = g_alpha[1], alpha3 = g_alpha[2];
    for (int c = tid; c < 192; c += 384) {
        float is = rsqrtf(v2[c] + EPS);
        bn2[c]       = alpha2 * g2[c] * is;
        bn2[192 + c] = b2[c] - m2p[c] * g2[c] * is;
    }
    if (tid < 32) {
        float is = rsqrtf(v3[tid] + EPS);
        bn3[tid]      = alpha3 * g3[tid] * is;
        bn3[32 + tid] = b3[tid] - m3p[tid] * g3[tid] * is;
    }

    auto load_chunk = [&](int t) {
        int ph = t / 9;
        int xi = (ph == 0) ? 2 : (ph == 1) ? 1 : (ph == 2) ? 0 : 3;
        int kc = t - ph * 9;
        int ky = kc / 3, ch = kc - ky * 3;
        int st = t % 3;
        uint32_t dA = sb + G_RING + st * 36864;
        uint32_t dB = dA + 12288;
        const __half* bsrc = g_w2t + (size_t)xi * 110592 + ky * 192 + ch * 64;
#pragma unroll
        for (int pp = 0; pp < 2; pp++) {
            int lin = pp * 384 + tid;
            int row = lin >> 3, c16 = lin & 7;
            int p = pbase + row; p = (p < 6271) ? p : 6271;
            int yq = p / 56; int pxq = p - yq * 56;
            const __half* asrc = g_h1t + (size_t)xi * PL +
                ((((size_t)img) * 114 + (yq + ky)) * 56 + pxq) * 192 + ch * 64;
            CP_ASYNC16(dA + SWZ(row * 128 + c16 * 16), (const char*)asrc + c16 * 16);
        }
#pragma unroll
        for (int pp = 0; pp < 4; pp++) {
            int lin = pp * 384 + tid;
            int row = lin >> 3, c16 = lin & 7;
            CP_ASYNC16(dB + SWZ(row * 128 + c16 * 16),
                       (const char*)(bsrc + (size_t)row * 576) + c16 * 16);
        }
    };

    int wm = (wid >= 6) ? 48 : 0;
    int wn = (wid % 6) * 32;

    int bR    = wn + ((lane >> 4) & 1) * 8 + (lane & 7);
    int bKsel = ((lane >> 3) & 1) * 8;
    int aM    = wm + (lane & 7) + ((lane >> 3) & 1) * 8;
    int aKsel = (lane >> 4) * 8;

    float acc[3][4][4], r3[3][4][4];
#pragma unroll
    for (int a = 0; a < 3; a++)
#pragma unroll
        for (int b = 0; b < 4; b++)
#pragma unroll
            for (int c = 0; c < 4; c++) { acc[a][b][c] = 0.0f; r3[a][b][c] = 0.0f; }

    float* uptr = (float*)(sbase + G_U + tid * 196);
    char*  h2s  = sbase + G_H2S;

    load_chunk(0); CP_COMMIT();
    load_chunk(1); CP_COMMIT();

    for (int t = 0; t < 36; t++) {
        if (t == 35) { CP_WAIT0(); } else { CP_WAIT1(); }
        __syncthreads();
        if (t + 2 < 36) { load_chunk(t + 2); CP_COMMIT(); }

        int st = t % 3;
        uint32_t cA = sb + G_RING + st * 36864;
        uint32_t cB = cA + 12288;
#pragma unroll
        for (int kk = 0; kk < 4; kk++) {
            uint32_t bf[4][2];
#pragma unroll
            for (int bb = 0; bb < 2; bb++) {
                uint32_t q0, q1, q2, q3;
                ldsm4(cB + SWZ((bR + bb * 16) * 128 + (kk * 16 + bKsel) * 2),
                      q0, q1, q2, q3);
                bf[2 * bb][0] = q0; bf[2 * bb][1] = q1;
                bf[2 * bb + 1][0] = q2; bf[2 * bb + 1][1] = q3;
            }
#pragma unroll
            for (int mi = 0; mi < 3; mi++) {
                uint32_t a0, a1, a2, a3;
                ldsm4(cA + SWZ((aM + mi * 16) * 128 + (kk * 16 + aKsel) * 2),
                      a0, a1, a2, a3);
#pragma unroll
                for (int ni = 0; ni < 4; ni++)
                    mma16816(acc[mi][ni], a0, a1, a2, a3, bf[ni][0], bf[ni][1]);
            }
        }

        if (t == 8) {
#pragma unroll
            for (int a = 0; a < 3; a++)
#pragma unroll
                for (int b = 0; b < 4; b++)
#pragma unroll
                    for (int c = 0; c < 4; c++) { r3[a][b][c] = acc[a][b][c]; acc[a][b][c] = 0.0f; }
        } else if (t == 17) {
#pragma unroll
            for (int a = 0; a < 3; a++)
#pragma unroll
                for (int b = 0; b < 4; b++)
#pragma unroll
                    for (int c = 0; c < 4; c++) {
                        int j = (a * 4 + b) * 4 + c;
                        uptr[j] = acc[a][b][c] + r3[a][b][c];
                        r3[a][b][c] = acc[a][b][c] - r3[a][b][c];
                        acc[a][b][c] = 0.0f;
                    }
        } else if (t == 26) {
#pragma unroll
            for (int a = 0; a < 3; a++)
#pragma unroll
                for (int b = 0; b < 4; b++)
#pragma unroll
                    for (int c = 0; c < 4; c++)
                        acc[a][b][c] += uptr[(a * 4 + b) * 4 + c];
            __syncthreads();
#pragma unroll
            for (int mi = 0; mi < 3; mi++) {
#pragma unroll
                for (int h = 0; h < 2; h++) {
                    int m = 2 * (wm + mi * 16 + (lane >> 2) + h * 8);
#pragma unroll
                    for (int ni = 0; ni < 4; ni++) {
                        int cc = wn + ni * 8 + 2 * (lane & 3);
                        float y0 = fmaf(acc[mi][ni][h * 2 + 0], bn2[cc],     bn2[192 + cc]);
                        float y1 = fmaf(acc[mi][ni][h * 2 + 1], bn2[cc + 1], bn2[192 + cc + 1]);
                        y0 = fminf(fmaxf(y0, 0.0f), 6.0f);
                        y1 = fminf(fmaxf(y1, 0.0f), 6.0f);
                        uint32_t pk = (uint32_t)__half_as_ushort(__float2half_rn(y0)) |
                                      ((uint32_t)__half_as_ushort(__float2half_rn(y1)) << 16);
                        *(uint32_t*)(h2s + (cc >> 6) * 24576 + SWZ(m * 128 + (cc & 63) * 2)) = pk;
                    }
                }
            }
#pragma unroll
            for (int a = 0; a < 3; a++)
#pragma unroll
                for (int b = 0; b < 4; b++)
#pragma unroll
                    for (int c = 0; c < 4; c++) acc[a][b][c] = 0.0f;
        }
    }
#pragma unroll
    for (int mi = 0; mi < 3; mi++) {
#pragma unroll
        for (int h = 0; h < 2; h++) {
            int m = 2 * (wm + mi * 16 + (lane >> 2) + h * 8) + 1;
#pragma unroll
            for (int ni = 0; ni < 4; ni++) {
                int cc = wn + ni * 8 + 2 * (lane & 3);
                float y0 = fmaf(r3[mi][ni][h * 2 + 0] - acc[mi][ni][h * 2 + 0],
                                bn2[cc],     bn2[192 + cc]);
                float y1 = fmaf(r3[mi][ni][h * 2 + 1] - acc[mi][ni][h * 2 + 1],
                                bn2[cc + 1], bn2[192 + cc + 1]);
                y0 = fminf(fmaxf(y0, 0.0f), 6.0f);
                y1 = fminf(fmaxf(y1, 0.0f), 6.0f);
                uint32_t pk = (uint32_t)__half_as_ushort(__float2half_rn(y0)) |
                              ((uint32_t)__half_as_ushort(__float2half_rn(y1)) << 16);
                *(uint32_t*)(h2s + (cc >> 6) * 24576 + SWZ(m * 128 + (cc & 63) * 2)) = pk;
            }
        }
    }
    __syncthreads();

    int wm3 = (wid >> 2) * 64;
    int wn3 = (wid & 3) * 8;
    float acc3[4][4];
#pragma unroll
    for (int a = 0; a < 4; a++)
#pragma unroll
        for (int c = 0; c < 4; c++) acc3[a][c] = 0.0f;

#pragma unroll
    for (int ch = 0; ch < 3; ch++) {
        uint32_t cA = sb + G_H2S + ch * 24576;
        uint32_t cB = sb + G_W3 + ch * 4096;
#pragma unroll
        for (int kk = 0; kk < 4; kk++) {
            uint32_t b0, b1;
            ldsm2(cB + SWZ((wn3 + (lane & 7)) * 128 +
                           (kk * 16 + ((lane >> 3) & 1) * 8) * 2), b0, b1);
#pragma unroll
            for (int mi = 0; mi < 4; mi++) {
                int m_loc = wm3 + mi * 16 + (lane & 7) + ((lane >> 3) & 1) * 8;
                int kh = kk * 16 + (lane >> 4) * 8;
                uint32_t a0, a1, a2, a3;
                ldsm4(cA + SWZ(m_loc * 128 + kh * 2), a0, a1, a2, a3);
                mma16816(acc3[mi], a0, a1, a2, a3, b0, b1);
            }
        }
    }

    const float* xi = x + (size_t)img * 32 * HW;
    float* oi = out + (size_t)img * 32 * HW;
#pragma unroll
    for (int mi = 0; mi < 4; mi++) {
#pragma unroll
        for (int h = 0; h < 2; h++) {
            int m = wm3 + mi * 16 + (lane >> 2) + h * 8;
            int P = pbase + (m >> 1);
            if (P < 6272) {
                int yq = P / 56, px = P - yq * 56;
                int pix = yq * 112 + 2 * px + (m & 1);
                int c = wn3 + 2 * (lane & 3);
                size_t i0 = (size_t)c * HW + pix;
                size_t i1 = i0 + HW;
                oi[i0] = fmaf(acc3[mi][h * 2 + 0], bn3[c],     bn3[32 + c])     + xi[i0];
                oi[i1] = fmaf(acc3[mi][h * 2 + 1], bn3[c + 1], bn3[32 + c + 1]) + xi[i1];
            }
        }
    }
}

// ---------------- launch ----------------------------------------------------
extern "C" void kernel_launch(void* const* d_in, const int* in_sizes, int n_in,
                              void* d_out, int out_size) {
    const float* x  = (const float*)d_in[0];
    const float* w1 = (const float*)d_in[1];
    const float* g1 = (const float*)d_in[2];
    const float* b1 = (const float*)d_in[3];
    const float* m1 = (const float*)d_in[4];
    const float* v1 = (const float*)d_in[5];
    const float* w2 = (const float*)d_in[6];
    const float* g2 = (const float*)d_in[7];
    const float* b2 = (const float*)d_in[8];
    const float* m2 = (const float*)d_in[9];
    const float* v2 = (const float*)d_in[10];
    const float* w3 = (const float*)d_in[11];
    const float* g3 = (const float*)d_in[12];
    const float* b3 = (const float*)d_in[13];
    const float* m3 = (const float*)d_in[14];
    const float* v3 = (const float*)d_in[15];
    float* out = (float*)d_out;

    cudaFuncSetAttribute(conv1w, cudaFuncAttributeMaxDynamicSharedMemorySize, W1_SMEM);
    cudaFuncSetAttribute(conv2w3, cudaFuncAttributeMaxDynamicSharedMemorySize, G_SMEM);

    stats_abs_all<<<dim3(148, 3), 256>>>(w1, w2, w3);
    stats_alpha_prep<<<dim3(148, 3), 256>>>(w1, w2, w3);
    stats_alpha_fin_all<<<3, 256>>>();

    conv1w<<<dim3(112, 16), 256, W1_SMEM>>>(x, g1, b1, m1, v1);
    conv2w3<<<dim3(66, 16), 384, G_SMEM>>>(g2, b2, m2, v2,
                                           g3, b3, m3, v3, x, out);
}